// round 12
// baseline (speedup 1.0000x reference)
#include <cuda_runtime.h>

#define BB 32
#define TT_IN 1024
#define TP 1025
#define EMB 384
#define GC 96
#define NWARPS 12
#define NKS 36            // total K-steps: 3 taps * 96 ch / 8
#define NCHUNK 10
#define SUBS 7            // m16-subtiles per chunk (10*7*16 = 1120 >= 1025)
#define ZWARPS 64         // tail-zero warps per batch
#define NPART 16          // 4 groups * 4 n-groups partials

#define CONV_BLOCKS (BB * 4 * NCHUNK)              // 1280
#define SW_SCAT (BB * TP)                          // 32800 scatter warps
#define SW_TOT  (SW_SCAT + BB * ZWARPS)            // + 2048 zero warps
#define SCAT_BLOCKS ((SW_TOT + NWARPS - 1) / NWARPS)   // 2904
#define TOTAL_BLOCKS (CONV_BLOCKS + SCAT_BLOCKS)       // 4184

// Scratch (device globals: no allocations allowed)
__device__ int          g_cum[BB * TP];
__device__ unsigned int g_wB[4 * NWARPS * NKS * 2 * 32];  // tf32 B fragments
__device__ float        g_part[NPART * BB * TP];          // pred partials

#define CVT_TF32(u, f) asm("cvt.rna.tf32.f32 %0, %1;" : "=r"(u) : "f"(f))

#define MMA_TF32(d0,d1,d2,d3, a0,a1,a2,a3, b0,b1)                          \
    asm("mma.sync.aligned.m16n8k8.row.col.f32.tf32.tf32.f32 "              \
        "{%0,%1,%2,%3}, {%4,%5,%6,%7}, {%8,%9}, {%0,%1,%2,%3};"            \
        : "+f"(d0), "+f"(d1), "+f"(d2), "+f"(d3)                           \
        : "r"(a0), "r"(a1), "r"(a2), "r"(a3), "r"(b0), "r"(b1))

// ---------------------------------------------------------------------------
// Merged prep: blocks [0,32) = per-batch cumsum; blocks >= 32 = pack conv1
// weights into tf32 mma B-fragment order (validated R4/R8/R9).
// ---------------------------------------------------------------------------
__global__ void prep_kernel(const int* __restrict__ dur,
                            const float* __restrict__ w1) {
    if (blockIdx.x < BB) {
        const int b = blockIdx.x;
        const int tid = threadIdx.x;           // 256 threads
        const int CH = 5;
        __shared__ int part[256];

        int base = tid * CH;
        int s = 0;
#pragma unroll
        for (int j = 0; j < CH; j++) {
            int p = base + j;
            if (p < TP) s += dur[b * TP + p];
        }
        part[tid] = s;
        __syncthreads();

        for (int off = 1; off < 256; off <<= 1) {
            int v = (tid >= off) ? part[tid - off] : 0;
            __syncthreads();
            part[tid] += v;
            __syncthreads();
        }

        int run = (tid > 0) ? part[tid - 1] : 0;
#pragma unroll
        for (int j = 0; j < CH; j++) {
            int p = base + j;
            if (p < TP) {
                run += dur[b * TP + p];
                g_cum[b * TP + p] = run;
            }
        }
    } else {
        int t = (blockIdx.x - BB) * blockDim.x + threadIdx.x;
        if (t >= 4 * NWARPS * NKS * 32) return;
        int lane = t & 31;
        int rest = t >> 5;
        int ks = rest % NKS;
        int nt = (rest / NKS) % NWARPS;
        int g  = rest / (NKS * NWARPS);

        int kk = ks / 12;
        int n  = nt * 8 + (lane >> 2);
        int C  = g * GC + n;
#pragma unroll
        for (int r = 0; r < 2; r++) {
            int i = (ks % 12) * 8 + (lane & 3) + 4 * r;
            float w = w1[C * (GC * 3) + i * 3 + kk];
            unsigned u; CVT_TF32(u, w);
            g_wB[(((g * NWARPS + nt) * NKS + ks) * 2 + r) * 32 + lane] = u;
        }
    }
}

// ---------------------------------------------------------------------------
// FUSED kernel, INTERLEAVED roles: for bid < 3*CONV_BLOCKS, every 3rd block
// is conv (cb = bid/3), the other two are scatter; the tail is scatter.
// Each scheduling wave thus mixes both roles; short-lived scatter blocks
// stream through while long-lived conv blocks accumulate SM residency, so
// scatter's DRAM traffic hides under conv's smem/tensor work.
// ---------------------------------------------------------------------------
__global__ __launch_bounds__(384)
void fused_kernel(const float* __restrict__ ph,
                  const float* __restrict__ sil,
                  const float* __restrict__ b1,
                  const float* __restrict__ w2,
                  float* __restrict__ out,
                  int t_out) {
    __shared__ unsigned int xsbuf[2][18 * 50 * 2];   // 2 x 7.2 KB
    __shared__ float4 P[NWARPS][32][3];              // 18 KB k-partials

    const int tid  = threadIdx.x;
    const int wid  = tid >> 5;
    const int lane = tid & 31;
    const int bid  = blockIdx.x;

    const bool is_conv = (bid % 3 == 0) && (bid < 3 * CONV_BLOCKS);

    if (is_conv) {
        // ================= CONV (R9 body) =================
        const int cb    = bid / 3;
        const int b     = cb & 31;
        const int g     = (cb >> 5) & 3;
        const int chunk = cb >> 7;
        const int tbase = chunk * (SUBS * 16);
        const int g4    = lane >> 2;
        const int t4    = lane & 3;
        const int ng    = wid & 3;        // n-group (3 n-tiles = 24 channels)
        const int kt    = wid >> 2;       // k-third = conv tap (0..2)

        // B fragments for this warp's 3 n-tiles x 12 K-steps (72 regs).
        unsigned int Breg0[12][3], Breg1[12][3];
#pragma unroll
        for (int j = 0; j < 3; j++) {
            const int nt = ng * 3 + j;
            const unsigned int* wb = g_wB + ((g * NWARPS + nt) * NKS) * 2 * 32 + lane;
#pragma unroll
            for (int ksl = 0; ksl < 12; ksl++) {
                const int ks = kt * 12 + ksl;
                Breg0[ksl][j] = wb[(ks * 2 + 0) * 32];
                Breg1[ksl][j] = wb[(ks * 2 + 1) * 32];
            }
        }

        // Epilogue constants (readback warps 0..3 only).
        float w2v[3][2], b1v[3][2];
        if (wid < 4) {
#pragma unroll
            for (int j = 0; j < 3; j++) {
#pragma unroll
                for (int h = 0; h < 2; h++) {
                    int C = g * GC + (wid * 3 + j) * 8 + t4 * 2 + h;
                    w2v[j][h] = w2[C];
                    b1v[j][h] = b1[C];
                }
            }
        }

        // Prologue: stage subtile 0 into buffer 0 (permuted pair layout).
        {
            const int ts0 = tbase;
#pragma unroll
            for (int i = 0; i < 5; i++) {
                int e = tid + i * 384;
                if (e < 18 * GC) {
                    int row = e / GC, col = e - row * GC;
                    int tg = ts0 - 1 + row;
                    float v = 0.f;
                    if ((unsigned)tg < TT_IN) v = ph[((size_t)b * TT_IN + tg) * EMB + g * GC + col];
                    else if (tg == TT_IN)     v = sil[g * GC + col];
                    unsigned u; CVT_TF32(u, v);
                    int ki = col >> 3, rem = col & 7;
                    xsbuf[0][(row * 50 + (rem & 3) * 12 + ki) * 2 + (rem >> 2)] = u;
                }
            }
        }
        __syncthreads();

        for (int sub = 0; sub < SUBS; sub++) {
            const int tsub0 = tbase + sub * 16;
            if (tsub0 >= TP) break;              // block-uniform
            const int cur = sub & 1;
            const bool have_next = (sub + 1 < SUBS) && (tbase + (sub + 1) * 16 < TP);

            // Prefetch next subtile's x into registers (warps 4..11).
            float xv[7];
            if (have_next && wid >= 4) {
                const int ts1 = tsub0 + 16;
#pragma unroll
                for (int i = 0; i < 7; i++) {
                    int e = (tid - 128) + i * 256;
                    float v = 0.f;
                    if (e < 18 * GC) {
                        int row = e / GC, col = e - row * GC;
                        int tg = ts1 - 1 + row;
                        if ((unsigned)tg < TT_IN) v = ph[((size_t)b * TT_IN + tg) * EMB + g * GC + col];
                        else if (tg == TT_IN)     v = sil[g * GC + col];
                    }
                    xv[i] = v;
                }
            }

            // MMA: rows (g4+kt, g4+8+kt), 12 K-steps via 6 LDS.128 pairs.
            float acc[3][4];
#pragma unroll
            for (int j = 0; j < 3; j++)
#pragma unroll
                for (int q = 0; q < 4; q++) acc[j][q] = 0.f;

            {
                const uint4* U = (const uint4*)xsbuf[cur];
                const int i0 = (g4 + kt) * 25 + t4 * 6;   // uint4 index
                const int i1 = i0 + 8 * 25;
#pragma unroll
                for (int p = 0; p < 6; p++) {
                    uint4 A0 = U[i0 + p];
                    uint4 A1 = U[i1 + p];
#pragma unroll
                    for (int j = 0; j < 3; j++)
                        MMA_TF32(acc[j][0], acc[j][1], acc[j][2], acc[j][3],
                                 A0.x, A1.x, A0.y, A1.y,
                                 Breg0[2 * p][j], Breg1[2 * p][j]);
#pragma unroll
                    for (int j = 0; j < 3; j++)
                        MMA_TF32(acc[j][0], acc[j][1], acc[j][2], acc[j][3],
                                 A0.z, A1.z, A0.w, A1.w,
                                 Breg0[2 * p + 1][j], Breg1[2 * p + 1][j]);
                }
            }

            // Publish pre-ReLU k-partials.
#pragma unroll
            for (int j = 0; j < 3; j++)
                P[wid][lane][j] = make_float4(acc[j][0], acc[j][1], acc[j][2], acc[j][3]);
            __syncthreads();

            if (wid < 4) {
                float vlo = 0.f, vhi = 0.f;
#pragma unroll
                for (int j = 0; j < 3; j++) {
                    float4 p0 = P[wid][lane][j];
                    float4 p1 = P[4 + wid][lane][j];
                    float4 p2 = P[8 + wid][lane][j];
                    float sx = p0.x + p1.x + p2.x;
                    float sy = p0.y + p1.y + p2.y;
                    float sz = p0.z + p1.z + p2.z;
                    float sw = p0.w + p1.w + p2.w;
                    vlo += w2v[j][0] * fmaxf(sx + b1v[j][0], 0.f)
                         + w2v[j][1] * fmaxf(sy + b1v[j][1], 0.f);
                    vhi += w2v[j][0] * fmaxf(sz + b1v[j][0], 0.f)
                         + w2v[j][1] * fmaxf(sw + b1v[j][1], 0.f);
                }
                vlo += __shfl_xor_sync(0xffffffffu, vlo, 1);
                vlo += __shfl_xor_sync(0xffffffffu, vlo, 2);
                vhi += __shfl_xor_sync(0xffffffffu, vhi, 1);
                vhi += __shfl_xor_sync(0xffffffffu, vhi, 2);
                if (t4 == 0) {
                    const size_t base = ((size_t)(g * 4 + wid) * BB + b) * TP;
                    int t = tsub0 + g4;
                    if (t < TP)     g_part[base + t] = vlo;
                    if (t + 8 < TP) g_part[base + t + 8] = vhi;
                }
            } else if (have_next) {
                const int nxt = cur ^ 1;
#pragma unroll
                for (int i = 0; i < 7; i++) {
                    int e = (tid - 128) + i * 256;
                    if (e < 18 * GC) {
                        int row = e / GC, col = e - row * GC;
                        unsigned u; CVT_TF32(u, xv[i]);
                        int ki = col >> 3, rem = col & 7;
                        xsbuf[nxt][(row * 50 + (rem & 3) * 12 + ki) * 2 + (rem >> 2)] = u;
                    }
                }
            }
            __syncthreads();
        }
    } else {
        // ================= SCATTER + TAIL-ZERO (interleaved) ================
        // Scatter block index: among bids < 3*CONV_BLOCKS, two of every three;
        // beyond that, all blocks.
        int sb;
        if (bid < 3 * CONV_BLOCKS) sb = (bid / 3) * 2 + (bid % 3) - 1;
        else                       sb = 2 * CONV_BLOCKS + (bid - 3 * CONV_BLOCKS);

        const int w = sb * NWARPS + wid;

        if (w < SW_SCAT) {
            const int b = w / TP;
            const int j = w - b * TP;

            const int hi = g_cum[b * TP + j];
            const int lo = j ? g_cum[b * TP + j - 1] : 0;
            const int d = hi - lo;
            if (d <= 0) return;

            const float4* src = (j < TT_IN)
                ? (const float4*)(ph + ((size_t)b * TT_IN + j) * EMB)
                : (const float4*)sil;
            float4 r0 = __ldcs(src + lane);
            float4 r1 = __ldcs(src + 32 + lane);
            float4 r2 = __ldcs(src + 64 + lane);

            float4* dst = (float4*)(out + ((size_t)b * t_out + lo) * EMB);
            for (int f = 0; f < d; f++, dst += EMB / 4) {
                __stcs(dst + lane,      r0);
                __stcs(dst + 32 + lane, r1);
                __stcs(dst + 64 + lane, r2);
            }
        } else if (w < SW_TOT) {
            const int zw = w - SW_SCAT;
            const int b  = zw / ZWARPS;
            const int zi = zw - b * ZWARPS;
            const int tot = g_cum[b * TP + TP - 1];
            const float4 z = make_float4(0.f, 0.f, 0.f, 0.f);
            for (int t = tot + zi; t < t_out; t += ZWARPS) {
                float4* dst = (float4*)(out + ((size_t)b * t_out + t) * EMB);
                __stcs(dst + lane,      z);
                __stcs(dst + 32 + lane, z);
                __stcs(dst + 64 + lane, z);
            }
        }
    }
}

// Sum 16 partials + b2 -> durations_pred (deterministic).
__global__ void pred_sum_kernel(const float* __restrict__ b2,
                                float* __restrict__ dpred) {
    int i = blockIdx.x * blockDim.x + threadIdx.x;
    if (i >= BB * TP) return;
    float s = b2[0];
#pragma unroll
    for (int q = 0; q < NPART; q++) s += g_part[(size_t)q * BB * TP + i];
    dpred[i] = s;
}

// ---------------------------------------------------------------------------
// Launch
// ---------------------------------------------------------------------------
extern "C" void kernel_launch(void* const* d_in, const int* in_sizes, int n_in,
                              void* d_out, int out_size) {
    const float* ph  = (const float*)d_in[0];   // [32,1024,384]
    const float* sil = (const float*)d_in[1];   // [384]
    const float* w1  = (const float*)d_in[2];   // [384,96,3]
    const float* b1  = (const float*)d_in[3];   // [384]
    const float* w2  = (const float*)d_in[4];   // [1,384,1]
    const float* b2  = (const float*)d_in[5];   // [1]
    const int*   dur = (const int*)d_in[6];     // [32,1025]

    const int t_out = (out_size - BB * TP) / (BB * EMB);

    float* out_exp  = (float*)d_out;                             // [B,t_out,EMB]
    float* out_pred = (float*)d_out + (size_t)BB * t_out * EMB;  // [B,TP]

    const int wblocks = (4 * NWARPS * NKS * 32 + 255) / 256;
    prep_kernel<<<BB + wblocks, 256>>>(dur, w1);

    fused_kernel<<<TOTAL_BLOCKS, 384>>>(ph, sil, b1, w2, out_exp, t_out);

    pred_sum_kernel<<<(BB * TP + 255) / 256, 256>>>(b2, out_pred);
}

// round 13
// speedup vs baseline: 1.0605x; 1.0605x over previous
#include <cuda_runtime.h>

#define BB 32
#define TT_IN 1024
#define TP 1025
#define EMB 384
#define GC 96
#define NWARPS 12
#define NKS 36            // total K-steps: 3 taps * 96 ch / 8
#define NCHUNK 10
#define SUBS 7            // m16-subtiles per chunk (10*7*16 = 1120 >= 1025)
#define ZWARPS 64         // tail-zero warps per batch
#define NPART 16          // 4 groups * 4 n-groups partials

#define SW_SCAT (BB * TP)                          // 32800 scatter warps
#define SW_TOT  (SW_SCAT + BB * ZWARPS)            // + 2048 zero warps

// Scratch (device globals: no allocations allowed)
__device__ int          g_cum[BB * TP];
__device__ unsigned int g_wB[4 * NWARPS * NKS * 2 * 32];  // tf32 B fragments
__device__ float        g_part[NPART * BB * TP];          // pred partials

#define CVT_TF32(u, f) asm("cvt.rna.tf32.f32 %0, %1;" : "=r"(u) : "f"(f))

#define MMA_TF32(d0,d1,d2,d3, a0,a1,a2,a3, b0,b1)                          \
    asm("mma.sync.aligned.m16n8k8.row.col.f32.tf32.tf32.f32 "              \
        "{%0,%1,%2,%3}, {%4,%5,%6,%7}, {%8,%9}, {%0,%1,%2,%3};"            \
        : "+f"(d0), "+f"(d1), "+f"(d2), "+f"(d3)                           \
        : "r"(a0), "r"(a1), "r"(a2), "r"(a3), "r"(b0), "r"(b1))

// ---------------------------------------------------------------------------
// Merged prep: blocks [0,32) = per-batch cumsum; blocks >= 32 = pack conv1
// weights into tf32 mma B-fragment order (validated R4/R8/R9).
// ---------------------------------------------------------------------------
__global__ void prep_kernel(const int* __restrict__ dur,
                            const float* __restrict__ w1) {
    if (blockIdx.x < BB) {
        const int b = blockIdx.x;
        const int tid = threadIdx.x;           // 256 threads
        const int CH = 5;
        __shared__ int part[256];

        int base = tid * CH;
        int s = 0;
#pragma unroll
        for (int j = 0; j < CH; j++) {
            int p = base + j;
            if (p < TP) s += dur[b * TP + p];
        }
        part[tid] = s;
        __syncthreads();

        for (int off = 1; off < 256; off <<= 1) {
            int v = (tid >= off) ? part[tid - off] : 0;
            __syncthreads();
            part[tid] += v;
            __syncthreads();
        }

        int run = (tid > 0) ? part[tid - 1] : 0;
#pragma unroll
        for (int j = 0; j < CH; j++) {
            int p = base + j;
            if (p < TP) {
                run += dur[b * TP + p];
                g_cum[b * TP + p] = run;
            }
        }
    } else {
        int t = (blockIdx.x - BB) * blockDim.x + threadIdx.x;
        if (t >= 4 * NWARPS * NKS * 32) return;
        int lane = t & 31;
        int rest = t >> 5;
        int ks = rest % NKS;
        int nt = (rest / NKS) % NWARPS;
        int g  = rest / (NKS * NWARPS);

        int kk = ks / 12;
        int n  = nt * 8 + (lane >> 2);
        int C  = g * GC + n;
#pragma unroll
        for (int r = 0; r < 2; r++) {
            int i = (ks % 12) * 8 + (lane & 3) + 4 * r;
            float w = w1[C * (GC * 3) + i * 3 + kk];
            unsigned u; CVT_TF32(u, w);
            g_wB[(((g * NWARPS + nt) * NKS + ks) * 2 + r) * 32 + lane] = u;
        }
    }
}

// ---------------------------------------------------------------------------
// tf32 tensor-core duration predictor (R9 body, unchanged — proven @ ~88us).
// grid = (BB, 4 groups, NCHUNK); block = 384 = 12 warps.
// ---------------------------------------------------------------------------
__global__ __launch_bounds__(384)
void conv_mma_kernel(const float* __restrict__ ph,
                     const float* __restrict__ sil,
                     const float* __restrict__ b1,
                     const float* __restrict__ w2) {
    __shared__ unsigned int xsbuf[2][18 * 50 * 2];   // 2 x 7.2 KB
    __shared__ float4 P[NWARPS][32][3];              // 18 KB k-partials

    const int b     = blockIdx.x;
    const int g     = blockIdx.y;
    const int chunk = blockIdx.z;
    const int tbase = chunk * (SUBS * 16);
    const int tid   = threadIdx.x;
    const int wid   = tid >> 5;
    const int lane  = tid & 31;
    const int g4    = lane >> 2;
    const int t4    = lane & 3;
    const int ng    = wid & 3;        // n-group (3 n-tiles = 24 channels)
    const int kt    = wid >> 2;       // k-third = conv tap (0..2)

    // B fragments for this warp's 3 n-tiles x 12 K-steps (72 regs).
    unsigned int Breg0[12][3], Breg1[12][3];
#pragma unroll
    for (int j = 0; j < 3; j++) {
        const int nt = ng * 3 + j;
        const unsigned int* wb = g_wB + ((g * NWARPS + nt) * NKS) * 2 * 32 + lane;
#pragma unroll
        for (int ksl = 0; ksl < 12; ksl++) {
            const int ks = kt * 12 + ksl;
            Breg0[ksl][j] = wb[(ks * 2 + 0) * 32];
            Breg1[ksl][j] = wb[(ks * 2 + 1) * 32];
        }
    }

    // Epilogue constants (readback warps 0..3 only).
    float w2v[3][2], b1v[3][2];
    if (wid < 4) {
#pragma unroll
        for (int j = 0; j < 3; j++) {
#pragma unroll
            for (int h = 0; h < 2; h++) {
                int C = g * GC + (wid * 3 + j) * 8 + t4 * 2 + h;
                w2v[j][h] = w2[C];
                b1v[j][h] = b1[C];
            }
        }
    }

    // Prologue: stage subtile 0 into buffer 0 (permuted pair layout).
    {
        const int ts0 = tbase;
#pragma unroll
        for (int i = 0; i < 5; i++) {
            int e = tid + i * 384;
            if (e < 18 * GC) {
                int row = e / GC, col = e - row * GC;
                int tg = ts0 - 1 + row;
                float v = 0.f;
                if ((unsigned)tg < TT_IN) v = ph[((size_t)b * TT_IN + tg) * EMB + g * GC + col];
                else if (tg == TT_IN)     v = sil[g * GC + col];
                unsigned u; CVT_TF32(u, v);
                int ki = col >> 3, rem = col & 7;
                xsbuf[0][(row * 50 + (rem & 3) * 12 + ki) * 2 + (rem >> 2)] = u;
            }
        }
    }
    __syncthreads();

    for (int sub = 0; sub < SUBS; sub++) {
        const int tsub0 = tbase + sub * 16;
        if (tsub0 >= TP) break;              // block-uniform
        const int cur = sub & 1;
        const bool have_next = (sub + 1 < SUBS) && (tbase + (sub + 1) * 16 < TP);

        // Prefetch next subtile's x into registers (warps 4..11).
        float xv[7];
        if (have_next && wid >= 4) {
            const int ts1 = tsub0 + 16;
#pragma unroll
            for (int i = 0; i < 7; i++) {
                int e = (tid - 128) + i * 256;
                float v = 0.f;
                if (e < 18 * GC) {
                    int row = e / GC, col = e - row * GC;
                    int tg = ts1 - 1 + row;
                    if ((unsigned)tg < TT_IN) v = ph[((size_t)b * TT_IN + tg) * EMB + g * GC + col];
                    else if (tg == TT_IN)     v = sil[g * GC + col];
                }
                xv[i] = v;
            }
        }

        // MMA: rows (g4+kt, g4+8+kt), 12 K-steps via 6 LDS.128 pairs.
        float acc[3][4];
#pragma unroll
        for (int j = 0; j < 3; j++)
#pragma unroll
            for (int q = 0; q < 4; q++) acc[j][q] = 0.f;

        {
            const uint4* U = (const uint4*)xsbuf[cur];
            const int i0 = (g4 + kt) * 25 + t4 * 6;   // uint4 index
            const int i1 = i0 + 8 * 25;
#pragma unroll
            for (int p = 0; p < 6; p++) {
                uint4 A0 = U[i0 + p];
                uint4 A1 = U[i1 + p];
#pragma unroll
                for (int j = 0; j < 3; j++)
                    MMA_TF32(acc[j][0], acc[j][1], acc[j][2], acc[j][3],
                             A0.x, A1.x, A0.y, A1.y,
                             Breg0[2 * p][j], Breg1[2 * p][j]);
#pragma unroll
                for (int j = 0; j < 3; j++)
                    MMA_TF32(acc[j][0], acc[j][1], acc[j][2], acc[j][3],
                             A0.z, A1.z, A0.w, A1.w,
                             Breg0[2 * p + 1][j], Breg1[2 * p + 1][j]);
            }
        }

        // Publish pre-ReLU k-partials.
#pragma unroll
        for (int j = 0; j < 3; j++)
            P[wid][lane][j] = make_float4(acc[j][0], acc[j][1], acc[j][2], acc[j][3]);
        __syncthreads();

        if (wid < 4) {
            float vlo = 0.f, vhi = 0.f;
#pragma unroll
            for (int j = 0; j < 3; j++) {
                float4 p0 = P[wid][lane][j];
                float4 p1 = P[4 + wid][lane][j];
                float4 p2 = P[8 + wid][lane][j];
                float sx = p0.x + p1.x + p2.x;
                float sy = p0.y + p1.y + p2.y;
                float sz = p0.z + p1.z + p2.z;
                float sw = p0.w + p1.w + p2.w;
                vlo += w2v[j][0] * fmaxf(sx + b1v[j][0], 0.f)
                     + w2v[j][1] * fmaxf(sy + b1v[j][1], 0.f);
                vhi += w2v[j][0] * fmaxf(sz + b1v[j][0], 0.f)
                     + w2v[j][1] * fmaxf(sw + b1v[j][1], 0.f);
            }
            vlo += __shfl_xor_sync(0xffffffffu, vlo, 1);
            vlo += __shfl_xor_sync(0xffffffffu, vlo, 2);
            vhi += __shfl_xor_sync(0xffffffffu, vhi, 1);
            vhi += __shfl_xor_sync(0xffffffffu, vhi, 2);
            if (t4 == 0) {
                const size_t base = ((size_t)(g * 4 + wid) * BB + b) * TP;
                int t = tsub0 + g4;
                if (t < TP)     g_part[base + t] = vlo;
                if (t + 8 < TP) g_part[base + t + 8] = vhi;
            }
        } else if (have_next) {
            const int nxt = cur ^ 1;
#pragma unroll
            for (int i = 0; i < 7; i++) {
                int e = (tid - 128) + i * 256;
                if (e < 18 * GC) {
                    int row = e / GC, col = e - row * GC;
                    unsigned u; CVT_TF32(u, xv[i]);
                    int ki = col >> 3, rem = col & 7;
                    xsbuf[nxt][(row * 50 + (rem & 3) * 12 + ki) * 2 + (rem >> 2)] = u;
                }
            }
        }
        __syncthreads();
    }
}

// ---------------------------------------------------------------------------
// SCATTER + tail-zero (own kernel: 26 regs, no smem -> co-resides with conv).
// ---------------------------------------------------------------------------
__global__ void scatter_kernel(const float* __restrict__ ph,
                               const float* __restrict__ sil,
                               float* __restrict__ out,
                               int t_out) {
    const int w = (blockIdx.x * blockDim.x + threadIdx.x) >> 5;
    const int lane = threadIdx.x & 31;

    if (w < SW_SCAT) {
        const int b = w / TP;
        const int j = w - b * TP;

        const int hi = g_cum[b * TP + j];
        const int lo = j ? g_cum[b * TP + j - 1] : 0;
        const int d = hi - lo;
        if (d <= 0) return;

        const float4* src = (j < TT_IN)
            ? (const float4*)(ph + ((size_t)b * TT_IN + j) * EMB)
            : (const float4*)sil;
        float4 r0 = __ldcs(src + lane);
        float4 r1 = __ldcs(src + 32 + lane);
        float4 r2 = __ldcs(src + 64 + lane);

        float4* dst = (float4*)(out + ((size_t)b * t_out + lo) * EMB);
        for (int f = 0; f < d; f++, dst += EMB / 4) {
            __stcs(dst + lane,      r0);
            __stcs(dst + 32 + lane, r1);
            __stcs(dst + 64 + lane, r2);
        }
    } else if (w < SW_TOT) {
        const int zw = w - SW_SCAT;
        const int b  = zw / ZWARPS;
        const int zi = zw - b * ZWARPS;
        const int tot = g_cum[b * TP + TP - 1];
        const float4 z = make_float4(0.f, 0.f, 0.f, 0.f);
        for (int t = tot + zi; t < t_out; t += ZWARPS) {
            float4* dst = (float4*)(out + ((size_t)b * t_out + t) * EMB);
            __stcs(dst + lane,      z);
            __stcs(dst + 32 + lane, z);
            __stcs(dst + 64 + lane, z);
        }
    }
}

// Sum 16 partials + b2 -> durations_pred (deterministic).
__global__ void pred_sum_kernel(const float* __restrict__ b2,
                                float* __restrict__ dpred) {
    int i = blockIdx.x * blockDim.x + threadIdx.x;
    if (i >= BB * TP) return;
    float s = b2[0];
#pragma unroll
    for (int q = 0; q < NPART; q++) s += g_part[(size_t)q * BB * TP + i];
    dpred[i] = s;
}

// ---------------------------------------------------------------------------
// Launch: forked-capture graph. prep -> {scatter on side stream} || {conv ->
// pred_sum on main stream} -> join. Streams/events are host objects created
// once (no device memory); event record/wait is the documented multi-stream
// capture pattern, so the whole thing stays graph-capturable.
// ---------------------------------------------------------------------------
extern "C" void kernel_launch(void* const* d_in, const int* in_sizes, int n_in,
                              void* d_out, int out_size) {
    const float* ph  = (const float*)d_in[0];   // [32,1024,384]
    const float* sil = (const float*)d_in[1];   // [384]
    const float* w1  = (const float*)d_in[2];   // [384,96,3]
    const float* b1  = (const float*)d_in[3];   // [384]
    const float* w2  = (const float*)d_in[4];   // [1,384,1]
    const float* b2  = (const float*)d_in[5];   // [1]
    const int*   dur = (const int*)d_in[6];     // [32,1025]

    const int t_out = (out_size - BB * TP) / (BB * EMB);

    float* out_exp  = (float*)d_out;                             // [B,t_out,EMB]
    float* out_pred = (float*)d_out + (size_t)BB * t_out * EMB;  // [B,TP]

    static cudaStream_t s2 = nullptr;
    static cudaEvent_t ev_fork = nullptr, ev_join = nullptr;
    if (s2 == nullptr) {
        cudaStreamCreateWithFlags(&s2, cudaStreamNonBlocking);
        cudaEventCreateWithFlags(&ev_fork, cudaEventDisableTiming);
        cudaEventCreateWithFlags(&ev_join, cudaEventDisableTiming);
    }

    const int wblocks = (4 * NWARPS * NKS * 32 + 255) / 256;
    prep_kernel<<<BB + wblocks, 256>>>(dur, w1);

    // Fork: side stream waits on prep, runs the DRAM-bound scatter.
    cudaEventRecord(ev_fork, 0);
    cudaStreamWaitEvent(s2, ev_fork, 0);
    {
        const int warps = SW_TOT;
        scatter_kernel<<<(warps * 32 + 255) / 256, 256, 0, s2>>>(ph, sil,
                                                                 out_exp, t_out);
    }

    // Main stream: smem/tensor-bound conv, then pred reduction.
    dim3 cgrid(BB, 4, NCHUNK);
    conv_mma_kernel<<<cgrid, 384>>>(ph, sil, b1, w2);
    pred_sum_kernel<<<(BB * TP + 255) / 256, 256>>>(b2, out_pred);

    // Join: main stream completes only after the scatter branch.
    cudaEventRecord(ev_join, s2);
    cudaStreamWaitEvent(0, ev_join, 0);
}

// round 14
// speedup vs baseline: 1.1120x; 1.0486x over previous
#include <cuda_runtime.h>

#define BB 32
#define TT_IN 1024
#define TP 1025
#define EMB 384
#define GC 96
#define NWARPS 12
#define NKS 36            // total K-steps: 3 taps * 96 ch / 8
#define NCHUNK 5
#define SUBS 7            // m32-subtiles per chunk (5*7*32 = 1120 >= 1025)
#define ROWS 32           // time rows per subtile
#define XR 34             // staged rows (ROWS + 2 halo)
#define XE (XR * GC)      // staged elements = 3264
#define ZWARPS 64         // tail-zero warps per batch
#define NPART 16          // 4 groups * 4 n-groups partials
#define PWARPS ((BB * TP + 31) / 32)   // pred-sum warps inside scatter

#define SW_SCAT (BB * TP)                          // 32800 scatter warps
#define SW_TOT  (SW_SCAT + BB * ZWARPS)            // + 2048 zero warps

// Dynamic smem: xs двух buffers of 34*50 ull (3400 u32 each), then P.
#define XS_U32   (XR * 50 * 2)                     // 3400 u32 per buffer
#define SMEM_BYTES (2 * XS_U32 * 4 + 2 * NWARPS * 32 * 3 * 16)   // 27200 + 36864

// Scratch (device globals: no allocations allowed)
__device__ int          g_cum[BB * TP];
__device__ unsigned int g_wB[4 * NWARPS * NKS * 2 * 32];  // tf32 B fragments
__device__ float        g_part[NPART * BB * TP];          // pred partials

#define CVT_TF32(u, f) asm("cvt.rna.tf32.f32 %0, %1;" : "=r"(u) : "f"(f))

#define MMA_TF32(d0,d1,d2,d3, a0,a1,a2,a3, b0,b1)                          \
    asm("mma.sync.aligned.m16n8k8.row.col.f32.tf32.tf32.f32 "              \
        "{%0,%1,%2,%3}, {%4,%5,%6,%7}, {%8,%9}, {%0,%1,%2,%3};"            \
        : "+f"(d0), "+f"(d1), "+f"(d2), "+f"(d3)                           \
        : "r"(a0), "r"(a1), "r"(a2), "r"(a3), "r"(b0), "r"(b1))

// Permuted pair staging address (validated R9): element (row, col) ->
// u32 index (row*50 + (rem&3)*12 + ki)*2 + (rem>>2), ki=col/8, rem=col%8.
__device__ __forceinline__ int stage_idx(int row, int col) {
    int ki = col >> 3, rem = col & 7;
    return (row * 50 + (rem & 3) * 12 + ki) * 2 + (rem >> 2);
}

// ---------------------------------------------------------------------------
// Merged prep: blocks [0,32) = per-batch cumsum; blocks >= 32 = pack conv1
// weights into tf32 mma B-fragment order (validated R4/R8/R9).
// ---------------------------------------------------------------------------
__global__ void prep_kernel(const int* __restrict__ dur,
                            const float* __restrict__ w1) {
    if (blockIdx.x < BB) {
        const int b = blockIdx.x;
        const int tid = threadIdx.x;           // 256 threads
        const int CH = 5;
        __shared__ int part[256];

        int base = tid * CH;
        int s = 0;
#pragma unroll
        for (int j = 0; j < CH; j++) {
            int p = base + j;
            if (p < TP) s += dur[b * TP + p];
        }
        part[tid] = s;
        __syncthreads();

        for (int off = 1; off < 256; off <<= 1) {
            int v = (tid >= off) ? part[tid - off] : 0;
            __syncthreads();
            part[tid] += v;
            __syncthreads();
        }

        int run = (tid > 0) ? part[tid - 1] : 0;
#pragma unroll
        for (int j = 0; j < CH; j++) {
            int p = base + j;
            if (p < TP) {
                run += dur[b * TP + p];
                g_cum[b * TP + p] = run;
            }
        }
    } else {
        int t = (blockIdx.x - BB) * blockDim.x + threadIdx.x;
        if (t >= 4 * NWARPS * NKS * 32) return;
        int lane = t & 31;
        int rest = t >> 5;
        int ks = rest % NKS;
        int nt = (rest / NKS) % NWARPS;
        int g  = rest / (NKS * NWARPS);

        int kk = ks / 12;
        int n  = nt * 8 + (lane >> 2);
        int C  = g * GC + n;
#pragma unroll
        for (int r = 0; r < 2; r++) {
            int i = (ks % 12) * 8 + (lane & 3) + 4 * r;
            float w = w1[C * (GC * 3) + i * 3 + kk];
            unsigned u; CVT_TF32(u, w);
            g_wB[(((g * NWARPS + nt) * NKS + ks) * 2 + r) * 32 + lane] = u;
        }
    }
}

// ---------------------------------------------------------------------------
// tf32 tensor-core duration predictor, m32 subtiles (2 m16 fragments/warp).
// grid = (BB, 4 groups, NCHUNK); block = 384 = 12 warps.
// Warp (ng = wid&3, kt = wid>>2): n-tiles {3ng..3ng+2}, conv tap kt.
// Barriers/prologues amortized over 32 rows instead of 16.
// ---------------------------------------------------------------------------
extern __shared__ unsigned int dsm[];

__global__ __launch_bounds__(384)
void conv_mma_kernel(const float* __restrict__ ph,
                     const float* __restrict__ sil,
                     const float* __restrict__ b1,
                     const float* __restrict__ w2) {
    unsigned int* xs[2] = { dsm, dsm + XS_U32 };
    float4* P = (float4*)(dsm + 2 * XS_U32);   // [q][wid][lane][j] = ((q*12+w)*32+l)*3+j

    const int b     = blockIdx.x;
    const int g     = blockIdx.y;
    const int chunk = blockIdx.z;
    const int tbase = chunk * (SUBS * ROWS);
    const int tid   = threadIdx.x;
    const int wid   = tid >> 5;
    const int lane  = tid & 31;
    const int g4    = lane >> 2;
    const int t4    = lane & 3;
    const int ng    = wid & 3;        // n-group (3 n-tiles = 24 channels)
    const int kt    = wid >> 2;       // k-third = conv tap (0..2)

    // B fragments for this warp's 3 n-tiles x 12 K-steps (72 regs).
    unsigned int Breg0[12][3], Breg1[12][3];
#pragma unroll
    for (int j = 0; j < 3; j++) {
        const int nt = ng * 3 + j;
        const unsigned int* wb = g_wB + ((g * NWARPS + nt) * NKS) * 2 * 32 + lane;
#pragma unroll
        for (int ksl = 0; ksl < 12; ksl++) {
            const int ks = kt * 12 + ksl;
            Breg0[ksl][j] = wb[(ks * 2 + 0) * 32];
            Breg1[ksl][j] = wb[(ks * 2 + 1) * 32];
        }
    }

    // Epilogue constants (readback warps 0..3 only).
    float w2v[3][2], b1v[3][2];
    if (wid < 4) {
#pragma unroll
        for (int j = 0; j < 3; j++) {
#pragma unroll
            for (int h = 0; h < 2; h++) {
                int C = g * GC + (wid * 3 + j) * 8 + t4 * 2 + h;
                w2v[j][h] = w2[C];
                b1v[j][h] = b1[C];
            }
        }
    }

    // Prologue: stage subtile 0 into buffer 0.
    {
        const int ts0 = tbase;
#pragma unroll
        for (int i = 0; i < 9; i++) {
            int e = tid + i * 384;
            if (e < XE) {
                int row = e / GC, col = e - row * GC;
                int tg = ts0 - 1 + row;
                float v = 0.f;
                if ((unsigned)tg < TT_IN) v = ph[((size_t)b * TT_IN + tg) * EMB + g * GC + col];
                else if (tg == TT_IN)     v = sil[g * GC + col];
                unsigned u; CVT_TF32(u, v);
                xs[0][stage_idx(row, col)] = u;
            }
        }
    }
    __syncthreads();

    for (int sub = 0; sub < SUBS; sub++) {
        const int tsub0 = tbase + sub * ROWS;
        if (tsub0 >= TP) break;              // block-uniform
        const int cur = sub & 1;
        const bool have_next = (sub + 1 < SUBS) && (tbase + (sub + 1) * ROWS < TP);

        // Prefetch next subtile's x into registers (warps 4..11, 256 thr).
        float xv[13];
        if (have_next && wid >= 4) {
            const int ts1 = tsub0 + ROWS;
#pragma unroll
            for (int i = 0; i < 13; i++) {
                int e = (tid - 128) + i * 256;
                float v = 0.f;
                if (e < XE) {
                    int row = e / GC, col = e - row * GC;
                    int tg = ts1 - 1 + row;
                    if ((unsigned)tg < TT_IN) v = ph[((size_t)b * TT_IN + tg) * EMB + g * GC + col];
                    else if (tg == TT_IN)     v = sil[g * GC + col];
                }
                xv[i] = v;
            }
        }

        // MMA: two m16 tiles (q=0,1), rows (q*16+g4+kt, +8), 12 K-steps each.
        float acc[2][3][4];
#pragma unroll
        for (int q = 0; q < 2; q++)
#pragma unroll
            for (int j = 0; j < 3; j++)
#pragma unroll
                for (int r = 0; r < 4; r++) acc[q][j][r] = 0.f;

        {
            const uint4* U = (const uint4*)xs[cur];
#pragma unroll
            for (int q = 0; q < 2; q++) {
                const int i0 = (q * 16 + g4 + kt) * 25 + t4 * 6;   // uint4 idx
                const int i1 = i0 + 8 * 25;
#pragma unroll
                for (int p = 0; p < 6; p++) {
                    uint4 A0 = U[i0 + p];
                    uint4 A1 = U[i1 + p];
#pragma unroll
                    for (int j = 0; j < 3; j++)
                        MMA_TF32(acc[q][j][0], acc[q][j][1], acc[q][j][2], acc[q][j][3],
                                 A0.x, A1.x, A0.y, A1.y,
                                 Breg0[2 * p][j], Breg1[2 * p][j]);
#pragma unroll
                    for (int j = 0; j < 3; j++)
                        MMA_TF32(acc[q][j][0], acc[q][j][1], acc[q][j][2], acc[q][j][3],
                                 A0.z, A1.z, A0.w, A1.w,
                                 Breg0[2 * p + 1][j], Breg1[2 * p + 1][j]);
                }
            }
        }

        // Publish pre-ReLU k-partials for both tiles.
#pragma unroll
        for (int q = 0; q < 2; q++)
#pragma unroll
            for (int j = 0; j < 3; j++)
                P[((q * NWARPS + wid) * 32 + lane) * 3 + j] =
                    make_float4(acc[q][j][0], acc[q][j][1], acc[q][j][2], acc[q][j][3]);
        __syncthreads();   // P complete; xs[cur] reads done

        if (wid < 4) {
#pragma unroll
            for (int q = 0; q < 2; q++) {
                float vlo = 0.f, vhi = 0.f;
#pragma unroll
                for (int j = 0; j < 3; j++) {
                    float4 p0 = P[((q * NWARPS + wid)     * 32 + lane) * 3 + j];
                    float4 p1 = P[((q * NWARPS + 4 + wid) * 32 + lane) * 3 + j];
                    float4 p2 = P[((q * NWARPS + 8 + wid) * 32 + lane) * 3 + j];
                    float sx = p0.x + p1.x + p2.x;
                    float sy = p0.y + p1.y + p2.y;
                    float sz = p0.z + p1.z + p2.z;
                    float sw = p0.w + p1.w + p2.w;
                    vlo += w2v[j][0] * fmaxf(sx + b1v[j][0], 0.f)
                         + w2v[j][1] * fmaxf(sy + b1v[j][1], 0.f);
                    vhi += w2v[j][0] * fmaxf(sz + b1v[j][0], 0.f)
                         + w2v[j][1] * fmaxf(sw + b1v[j][1], 0.f);
                }
                vlo += __shfl_xor_sync(0xffffffffu, vlo, 1);
                vlo += __shfl_xor_sync(0xffffffffu, vlo, 2);
                vhi += __shfl_xor_sync(0xffffffffu, vhi, 1);
                vhi += __shfl_xor_sync(0xffffffffu, vhi, 2);
                if (t4 == 0) {
                    const size_t base = ((size_t)(g * 4 + wid) * BB + b) * TP;
                    int t = tsub0 + q * 16 + g4;
                    if (t < TP)     g_part[base + t] = vlo;
                    if (t + 8 < TP) g_part[base + t + 8] = vhi;
                }
            }
        } else if (have_next) {
            const int nxt = cur ^ 1;
#pragma unroll
            for (int i = 0; i < 13; i++) {
                int e = (tid - 128) + i * 256;
                if (e < XE) {
                    int row = e / GC, col = e - row * GC;
                    unsigned u; CVT_TF32(u, xv[i]);
                    xs[nxt][stage_idx(row, col)] = u;
                }
            }
        }
        __syncthreads();   // xs[nxt] visible; P free for reuse
    }
}

// ---------------------------------------------------------------------------
// SCATTER + tail-zero + pred-sum, one kernel (R9-validated bodies).
// ---------------------------------------------------------------------------
__global__ void scatter_kernel(const float* __restrict__ ph,
                               const float* __restrict__ sil,
                               const float* __restrict__ b2,
                               float* __restrict__ out,
                               float* __restrict__ dpred,
                               int t_out) {
    const int w = (blockIdx.x * blockDim.x + threadIdx.x) >> 5;
    const int lane = threadIdx.x & 31;

    if (w < SW_SCAT) {
        const int b = w / TP;
        const int j = w - b * TP;

        const int hi = g_cum[b * TP + j];
        const int lo = j ? g_cum[b * TP + j - 1] : 0;
        const int d = hi - lo;
        if (d <= 0) return;

        const float4* src = (j < TT_IN)
            ? (const float4*)(ph + ((size_t)b * TT_IN + j) * EMB)
            : (const float4*)sil;
        float4 r0 = __ldcs(src + lane);
        float4 r1 = __ldcs(src + 32 + lane);
        float4 r2 = __ldcs(src + 64 + lane);

        float4* dst = (float4*)(out + ((size_t)b * t_out + lo) * EMB);
        for (int f = 0; f < d; f++, dst += EMB / 4) {
            __stcs(dst + lane,      r0);
            __stcs(dst + 32 + lane, r1);
            __stcs(dst + 64 + lane, r2);
        }
    } else if (w < SW_TOT) {
        const int zw = w - SW_SCAT;
        const int b  = zw / ZWARPS;
        const int zi = zw - b * ZWARPS;
        const int tot = g_cum[b * TP + TP - 1];
        const float4 z = make_float4(0.f, 0.f, 0.f, 0.f);
        for (int t = tot + zi; t < t_out; t += ZWARPS) {
            float4* dst = (float4*)(out + ((size_t)b * t_out + t) * EMB);
            __stcs(dst + lane,      z);
            __stcs(dst + 32 + lane, z);
            __stcs(dst + 64 + lane, z);
        }
    } else {
        const int pw = w - SW_TOT;
        if (pw >= PWARPS) return;
        const int i = pw * 32 + lane;
        if (i >= BB * TP) return;
        float s = b2[0];
#pragma unroll
        for (int q = 0; q < NPART; q++) s += g_part[(size_t)q * BB * TP + i];
        dpred[i] = s;
    }
}

// ---------------------------------------------------------------------------
// Launch
// ---------------------------------------------------------------------------
extern "C" void kernel_launch(void* const* d_in, const int* in_sizes, int n_in,
                              void* d_out, int out_size) {
    const float* ph  = (const float*)d_in[0];   // [32,1024,384]
    const float* sil = (const float*)d_in[1];   // [384]
    const float* w1  = (const float*)d_in[2];   // [384,96,3]
    const float* b1  = (const float*)d_in[3];   // [384]
    const float* w2  = (const float*)d_in[4];   // [1,384,1]
    const float* b2  = (const float*)d_in[5];   // [1]
    const int*   dur = (const int*)d_in[6];     // [32,1025]

    const int t_out = (out_size - BB * TP) / (BB * EMB);

    float* out_exp  = (float*)d_out;                             // [B,t_out,EMB]
    float* out_pred = (float*)d_out + (size_t)BB * t_out * EMB;  // [B,TP]

    const int wblocks = (4 * NWARPS * NKS * 32 + 255) / 256;
    prep_kernel<<<BB + wblocks, 256>>>(dur, w1);

    cudaFuncSetAttribute(conv_mma_kernel,
                         cudaFuncAttributeMaxDynamicSharedMemorySize, SMEM_BYTES);
    dim3 cgrid(BB, 4, NCHUNK);
    conv_mma_kernel<<<cgrid, 384, SMEM_BYTES>>>(ph, sil, b1, w2);

    const int warps = SW_TOT + PWARPS;
    scatter_kernel<<<(warps * 32 + 255) / 256, 256>>>(ph, sil, b2,
                                                      out_exp, out_pred, t_out);
}